// round 1
// baseline (speedup 1.0000x reference)
#include <cuda_runtime.h>
#include <math.h>
#include <stdint.h>

// Problem constants (fixed by the dataset)
#define NN      4096
#define MM      2048
#define DVV     3
#define DCC     6
#define EE      (NN*DVV)      // 12288
#define BB      2048
#define NITER   5
#define THREADS 512

// SMEM: buf (E floats) | llr (N floats) | sgn (E bytes)
#define SMEM_BYTES (EE*4 + NN*4 + EE)

// Persistent scratch (static __device__ globals: allowed; no runtime alloc)
__device__ int g_cnt[MM];
__device__ int g_tmp[EE];       // g_tmp[m*6 + slot] = edge id (atomic order)
__device__ int g_cne[MM * 8];   // sorted per-CN edge lists, padded to 8 for int4 loads

// ---------------------------------------------------------------------------
// Prep kernels: build deterministic per-CN edge lists each launch
// ---------------------------------------------------------------------------
__global__ void prep_zero()
{
    int i = blockIdx.x * blockDim.x + threadIdx.x;
    if (i < MM) g_cnt[i] = 0;
}

__global__ void prep_fill(const int* __restrict__ cn_idx)
{
    int e = blockIdx.x * blockDim.x + threadIdx.x;
    if (e < EE) {
        int m = cn_idx[e];
        int p = atomicAdd(&g_cnt[m], 1);
        g_tmp[m * DCC + p] = e;
    }
}

__global__ void prep_sort()
{
    int m = blockIdx.x * blockDim.x + threadIdx.x;
    if (m >= MM) return;
    int a[DCC];
#pragma unroll
    for (int j = 0; j < DCC; j++) a[j] = g_tmp[m * DCC + j];
    // bubble sort (15 compare-swaps) -> deterministic increasing edge order,
    // which matches jax's scatter-add accumulation order.
#pragma unroll
    for (int i = 0; i < DCC - 1; i++)
#pragma unroll
        for (int j = 0; j < DCC - 1 - i; j++)
            if (a[j] > a[j + 1]) { int t = a[j]; a[j] = a[j + 1]; a[j + 1] = t; }
#pragma unroll
    for (int j = 0; j < DCC; j++) g_cne[m * 8 + j] = a[j];
    g_cne[m * 8 + 6] = 0;
    g_cne[m * 8 + 7] = 0;
}

// ---------------------------------------------------------------------------
// Main BP kernel: one CTA per batch row, all state in SMEM
// ---------------------------------------------------------------------------
__global__ __launch_bounds__(THREADS, 2)
void bp_kernel(const float* __restrict__ noise_r,
               const float* __restrict__ w,
               float* __restrict__ out)
{
    extern __shared__ unsigned char smem_raw[];
    float* buf = reinterpret_cast<float*>(smem_raw);          // E floats: msg_vn <-> logt <-> msg_cn
    float* llr = buf + EE;                                    // N floats
    unsigned char* sgn = reinterpret_cast<unsigned char*>(llr + NN); // E bytes

    const int row = blockIdx.x;
    const int tid = threadIdx.x;
    const float* nr = noise_r + (size_t)row * NN;

    // Constants replicating the reference exactly
    const float NO_F  = (float)0.3981071705534972;            // 10^-0.4
    const float NSTD  = sqrtf((float)0.1990535852767486);     // sqrt(no/2) in f32
    const float CLIP  = (float)(1.0 - 1e-7);                  // 0.99999988079071f
    const float EPS   = 1e-12f;

    // llr init + msg_vn init
    for (int v = tid; v < NN; v += THREADS) {
        float y = 1.0f + NSTD * nr[v];
        float l = (4.0f * y) / NO_F;
        llr[v] = l;
        buf[3 * v + 0] = l;
        buf[3 * v + 1] = l;
        buf[3 * v + 2] = l;
    }
    __syncthreads();

    for (int it = 0; it < NITER; ++it) {
        // ---- forward: per edge, t = tanh(0.5*msg*w), store log|t|+eps and sign
        for (int e = tid; e < EE; e += THREADS) {
            float x = buf[e] * __ldg(&w[e]);
            float t = tanhf(0.5f * x);
            sgn[e]  = (t < 0.0f) ? (unsigned char)1 : (unsigned char)0;
            buf[e]  = logf(fabsf(t) + EPS);
        }
        __syncthreads();

        // ---- check-node update: gather 6 (sorted order), exclusive sums, write msg_cn in place
        for (int m = tid; m < MM; m += THREADS) {
            const int4 ea = *reinterpret_cast<const int4*>(&g_cne[m * 8]);
            const int2 eb = *reinterpret_cast<const int2*>(&g_cne[m * 8 + 4]);
            int e[6] = { ea.x, ea.y, ea.z, ea.w, eb.x, eb.y };
            float l[6];
            int   s[6];
            float sum = 0.0f;
            int   cnt = 0;
#pragma unroll
            for (int j = 0; j < 6; j++) {
                l[j] = buf[e[j]];
                s[j] = (int)sgn[e[j]];
                sum += l[j];            // sequential, increasing-edge order (matches ref)
                cnt += s[j];
            }
#pragma unroll
            for (int j = 0; j < 6; j++) {
                float el   = sum - l[j];
                float mag  = fminf(expf(el), CLIP);
                float esgn = 1.0f - 2.0f * (float)((cnt - s[j]) & 1);
                buf[e[j]]  = esgn * 2.0f * atanhf(mag);
            }
        }
        __syncthreads();

        // ---- variable-node update: per VN the 3 edges are contiguous
        const bool last = (it == NITER - 1);
        for (int v = tid; v < NN; v += THREADS) {
            float m0 = buf[3 * v + 0];
            float m1 = buf[3 * v + 1];
            float m2 = buf[3 * v + 2];
            float lt = llr[v] + ((m0 + m1) + m2);
            if (last) {
                out[(size_t)row * NN + v] = lt;
            } else {
                buf[3 * v + 0] = lt - m0;
                buf[3 * v + 1] = lt - m1;
                buf[3 * v + 2] = lt - m2;
            }
        }
        __syncthreads();
    }
}

// ---------------------------------------------------------------------------
// Launch
// ---------------------------------------------------------------------------
extern "C" void kernel_launch(void* const* d_in, const int* in_sizes, int n_in,
                              void* d_out, int out_size)
{
    const float* noise_r = (const float*)d_in[0];
    // d_in[1] = noise_i (unused by the reference)
    const float* weights = (const float*)d_in[2];
    // d_in[3] = vn_idx (structural: e/3)
    const int*   cn_idx  = (const int*)d_in[4];
    float* out = (float*)d_out;

    (void)in_sizes; (void)n_in; (void)out_size;

    cudaFuncSetAttribute(bp_kernel, cudaFuncAttributeMaxDynamicSharedMemorySize, SMEM_BYTES);

    prep_zero<<<(MM + 255) / 256, 256>>>();
    prep_fill<<<(EE + 255) / 256, 256>>>(cn_idx);
    prep_sort<<<(MM + 255) / 256, 256>>>();

    bp_kernel<<<BB, THREADS, SMEM_BYTES>>>(noise_r, weights, out);
}

// round 2
// speedup vs baseline: 2.1739x; 2.1739x over previous
#include <cuda_runtime.h>
#include <math.h>
#include <stdint.h>

// Problem constants (fixed by the dataset)
#define NN      4096
#define MM      2048
#define DVV     3
#define DCC     6
#define EE      (NN*DVV)      // 12288
#define BB      2048
#define NITER   5
#define THREADS 512
#define CN_PER_THREAD (MM/THREADS)   // 4

// SMEM: buf (E floats, msg_vn <-> msg_cn) | llr (N floats)
#define SMEM_BYTES (EE*4 + NN*4)     // 64 KB

// ---------------------------------------------------------------------------
// MUFU intrinsics (guaranteed fast path regardless of compile flags)
// ---------------------------------------------------------------------------
__device__ __forceinline__ float ex2a(float x){ float r; asm("ex2.approx.ftz.f32 %0, %1;" : "=f"(r) : "f"(x)); return r; }
__device__ __forceinline__ float lg2a(float x){ float r; asm("lg2.approx.ftz.f32 %0, %1;" : "=f"(r) : "f"(x)); return r; }
__device__ __forceinline__ float rcpa(float x){ float r; asm("rcp.approx.ftz.f32 %0, %1;" : "=f"(r) : "f"(x)); return r; }

// ---------------------------------------------------------------------------
// Persistent scratch (static globals: no runtime allocation)
// ---------------------------------------------------------------------------
__device__ int   g_cnt[MM];
__device__ int   g_tmp[EE];        // g_tmp[m*6+slot] = edge id (atomic order)
__device__ uint4 g_cnp[MM * 3];    // per CN: [8 x u16 byte-offsets][8 x f32 weights]

// ---------------------------------------------------------------------------
// Prep kernels (deterministic after the sort)
// ---------------------------------------------------------------------------
__global__ void prep_zero()
{
    int i = blockIdx.x * blockDim.x + threadIdx.x;
    if (i < MM) g_cnt[i] = 0;
}

__global__ void prep_fill(const int* __restrict__ cn_idx)
{
    int e = blockIdx.x * blockDim.x + threadIdx.x;
    if (e < EE) {
        int m = cn_idx[e];
        int p = atomicAdd(&g_cnt[m], 1);
        g_tmp[m * DCC + p] = e;
    }
}

__global__ void prep_pack(const float* __restrict__ w)
{
    int m = blockIdx.x * blockDim.x + threadIdx.x;
    if (m >= MM) return;
    int a[DCC];
#pragma unroll
    for (int j = 0; j < DCC; j++) a[j] = g_tmp[m * DCC + j];
    // sort ascending -> deterministic edge order matching jax scatter-add
#pragma unroll
    for (int i = 0; i < DCC - 1; i++)
#pragma unroll
        for (int j = 0; j < DCC - 1 - i; j++)
            if (a[j] > a[j + 1]) { int t = a[j]; a[j] = a[j + 1]; a[j + 1] = t; }

    uint4 iw;   // 8 x u16 pre-scaled byte offsets (e*4), slots 6,7 = 0
    iw.x = (unsigned)(a[0] * 4) | ((unsigned)(a[1] * 4) << 16);
    iw.y = (unsigned)(a[2] * 4) | ((unsigned)(a[3] * 4) << 16);
    iw.z = (unsigned)(a[4] * 4) | ((unsigned)(a[5] * 4) << 16);
    iw.w = 0;
    g_cnp[m * 3 + 0] = iw;

    float4 w0, w1;
    w0.x = w[a[0]]; w0.y = w[a[1]]; w0.z = w[a[2]]; w0.w = w[a[3]];
    w1.x = w[a[4]]; w1.y = w[a[5]]; w1.z = 0.0f;   w1.w = 0.0f;
    g_cnp[m * 3 + 1] = *reinterpret_cast<uint4*>(&w0);
    g_cnp[m * 3 + 2] = *reinterpret_cast<uint4*>(&w1);
}

// ---------------------------------------------------------------------------
// Main BP kernel: one CTA per batch row, all state in SMEM, log2 domain
// ---------------------------------------------------------------------------
__global__ __launch_bounds__(THREADS, 2)
void bp_kernel(const float* __restrict__ noise_r,
               float* __restrict__ out)
{
    extern __shared__ unsigned char smem_raw[];
    float* buf = reinterpret_cast<float*>(smem_raw);   // E floats
    float* llr = buf + EE;                             // N floats

    const int row = blockIdx.x;
    const int tid = threadIdx.x;
    const float* nr = noise_r + (size_t)row * NN;

    const float NO_F   = 0.3981071705534972f;          // 10^-0.4
    const float NSTD   = 0.44615420f;                  // sqrtf(no/2) in f32
    const float CLIP   = 0.99999988079071044921875f;   // float(1 - 1e-7)
    const float EPS    = 1e-12f;
    const float LOG2E  = 1.4426950408889634f;
    const float LN2    = 0.6931471805599453f;

    // llr init + msg_vn init
    for (int v = tid; v < NN; v += THREADS) {
        float y = 1.0f + NSTD * nr[v];
        float l = (4.0f * y) / NO_F;
        llr[v] = l;
        buf[3 * v + 0] = l;
        buf[3 * v + 1] = l;
        buf[3 * v + 2] = l;
    }
    __syncthreads();

    for (int it = 0; it < NITER; ++it) {
        // ---- check-node pass (forward tanh/log fused in, registers only) ----
#pragma unroll
        for (int k = 0; k < CN_PER_THREAD; ++k) {
            const int m = tid + k * THREADS;
            const uint4 iw = __ldg(&g_cnp[m * 3 + 0]);
            const uint4 wa = __ldg(&g_cnp[m * 3 + 1]);
            const uint4 wb = __ldg(&g_cnp[m * 3 + 2]);

            unsigned off[6];
            off[0] = iw.x & 0xFFFFu;  off[1] = iw.x >> 16;
            off[2] = iw.y & 0xFFFFu;  off[3] = iw.y >> 16;
            off[4] = iw.z & 0xFFFFu;  off[5] = iw.z >> 16;
            float wgt[6];
            wgt[0] = __uint_as_float(wa.x); wgt[1] = __uint_as_float(wa.y);
            wgt[2] = __uint_as_float(wa.z); wgt[3] = __uint_as_float(wa.w);
            wgt[4] = __uint_as_float(wb.x); wgt[5] = __uint_as_float(wb.y);

            float    l2[6];
            unsigned sb[6];
            float    sum  = 0.0f;
            unsigned sxor = 0u;
#pragma unroll
            for (int j = 0; j < 6; ++j) {
                float msg = *reinterpret_cast<const float*>(smem_raw + off[j]);
                float x   = msg * wgt[j];
                sb[j]     = __float_as_uint(x) & 0x80000000u;
                // |tanh(x/2)| = (1-u)/(1+u), u = e^{-|x|} = 2^{-|x|*log2e}
                float u   = ex2a(-fabsf(x) * LOG2E);
                float t   = (1.0f - u) * rcpa(1.0f + u);
                l2[j]     = lg2a(t + EPS);     // log2(|t| + eps)
                sum      += l2[j];             // ascending edge order (matches ref)
                sxor     ^= sb[j];
            }
#pragma unroll
            for (int j = 0; j < 6; ++j) {
                float el  = sum - l2[j];
                float mg  = fminf(ex2a(el), CLIP);        // clip(exp(excl_log))
                float r   = (1.0f + mg) * rcpa(1.0f - mg);
                float mag = lg2a(r) * LN2;                // 2*atanh(mg), >= 0
                unsigned bits = __float_as_uint(mag) | (sxor ^ sb[j]);
                *reinterpret_cast<float*>(smem_raw + off[j]) = __uint_as_float(bits);
            }
        }
        __syncthreads();

        // ---- variable-node pass: the 3 edges of VN v are contiguous ----
        const bool last = (it == NITER - 1);
        for (int v = tid; v < NN; v += THREADS) {
            float m0 = buf[3 * v + 0];
            float m1 = buf[3 * v + 1];
            float m2 = buf[3 * v + 2];
            float s  = (m0 + m1) + m2;      // ascending edge order
            float lt = llr[v] + s;
            if (last) {
                out[(size_t)row * NN + v] = lt;
            } else {
                buf[3 * v + 0] = lt - m0;
                buf[3 * v + 1] = lt - m1;
                buf[3 * v + 2] = lt - m2;
            }
        }
        __syncthreads();
    }
}

// ---------------------------------------------------------------------------
// Launch
// ---------------------------------------------------------------------------
extern "C" void kernel_launch(void* const* d_in, const int* in_sizes, int n_in,
                              void* d_out, int out_size)
{
    const float* noise_r = (const float*)d_in[0];
    // d_in[1] = noise_i (unused by the reference)
    const float* weights = (const float*)d_in[2];
    // d_in[3] = vn_idx (structural: e/3)
    const int*   cn_idx  = (const int*)d_in[4];
    float* out = (float*)d_out;

    (void)in_sizes; (void)n_in; (void)out_size;

    cudaFuncSetAttribute(bp_kernel, cudaFuncAttributeMaxDynamicSharedMemorySize, SMEM_BYTES);

    prep_zero<<<(MM + 255) / 256, 256>>>();
    prep_fill<<<(EE + 255) / 256, 256>>>(cn_idx);
    prep_pack<<<(MM + 255) / 256, 256>>>(weights);

    bp_kernel<<<BB, THREADS, SMEM_BYTES>>>(noise_r, out);
}